// round 14
// baseline (speedup 1.0000x reference)
#include <cuda_runtime.h>
#include <math.h>

#define BB 16
#define TT 1024
#define IND 64
#define OUTD 64
#define HHD 512
#define NND 128
#define MMD 40
#define KTOT 616        // IND + HHD + MMD, order [x|h|r]
#define KP4  157        // padded row stride in float4
#define KPAD 628
#define NCTA 128
#define NMEM 16
#define NGEMM 112
#define NTHR 512
#define RWS 20          // gate rows per gemm CTA
#define EPSV 1e-8f
#define RCACHE 80       // projection rows 0..79 cached in smem

// ---------------- persistent global state ----------------
__device__ __align__(16) float g_h[2][BB][HHD];
__device__ __align__(16) float g_r[2][BB][MMD];
__device__ unsigned g_hflags[NGEMM * 32];  // h(t)-ready, one per gemm CTA
__device__ unsigned g_rflags[NMEM * 32];   // r(t)-ready, one per mem CTA
__device__ unsigned g_gen = 0;             // launch generation

static __device__ __forceinline__ unsigned ld_acq(const unsigned* p) {
    unsigned v;
    asm volatile("ld.acquire.gpu.global.u32 %0, [%1];" : "=r"(v) : "l"(p) : "memory");
    return v;
}
static __device__ __forceinline__ void st_rel(unsigned* p, unsigned v) {
    asm volatile("st.release.gpu.global.u32 [%0], %1;" :: "l"(p), "r"(v) : "memory");
}

static __device__ __forceinline__ void wait_hflags(unsigned k) {
    if (threadIdx.x < 32) {
        for (;;) {
            bool ok = true;
            #pragma unroll
            for (int q = 0; q < 4; q++) {
                int f = threadIdx.x + 32 * q;
                if (f < NGEMM)
                    ok &= ((int)(ld_acq(&g_hflags[f * 32]) - k) >= 0);
            }
            if (__all_sync(0xffffffffu, ok)) break;
        }
    }
    __syncthreads();
}

struct __align__(16) GemmS {
    alignas(16) float W[RWS * KPAD];       // gate-weight slice [x|h|r]
    alignas(16) float inp[BB * KPAD];      // staged [x|h]
    alignas(16) float red[32 * 16 * RWS];  // split-K partials
    float gate[RWS * BB];
    float bias[RWS];
    float cst[5 * BB];
};
struct __align__(16) MemS {
    alignas(16) float pw[RCACHE * HHD];    // projection rows 0..79
    alignas(16) float mem[NND * 41];
    float rred[320];
    float proj[NND];
    float key[MMD];
    float ev[MMD];
    float av[MMD];
    float z[NND];
    float wsm[NND];
    float rsc[16];
    float scal[4];                         // [0]=||key||+eps, [1]=beta
};
struct __align__(16) Smem {
    union { GemmS g; MemS m; } u;
    unsigned genv;
};

static __device__ __forceinline__ const float* prow(int r,
    const float* W_k, const float* W_b, const float* W_e, const float* W_a)
{
    if (r < 40)  return W_k + r * HHD;
    if (r == 40) return W_b;
    if (r <= 80) return W_e + (r - 41) * HHD;
    return W_a + (r - 81) * HHD;
}

#define DOT4(acc, wv, iv) \
    acc += wv.x*iv.x; acc += wv.y*iv.y; acc += wv.z*iv.z; acc += wv.w*iv.w;

// xh-part GEMM (576 dims = f4 0..143), conflict-free interleaved mapping (R7).
static __device__ __forceinline__ void gemm_xh(GemmS& G, int tid) {
    const int kc = tid >> 4, tile = tid & 15;
    const int rg = tile & 3, bg = tile >> 2;
    const int koff = (kc < 16) ? kc * 5 : 80 + (kc - 16) * 4;
    const int klen = (kc < 16) ? 5 : 4;
    const float4* W4 = reinterpret_cast<const float4*>(G.W);
    const float4* I4 = reinterpret_cast<const float4*>(G.inp);
    float a[20];
    #pragma unroll
    for (int q = 0; q < 20; q++) a[q] = 0.f;
    #pragma unroll 5
    for (int q = 0; q < klen; q++) {
        float4 wv[5], iv[4];
        #pragma unroll
        for (int i = 0; i < 5; i++) wv[i] = W4[(rg + 4 * i) * KP4 + koff + q];
        #pragma unroll
        for (int j = 0; j < 4; j++) iv[j] = I4[(bg + 4 * j) * KP4 + koff + q];
        #pragma unroll
        for (int i = 0; i < 5; i++) {
            #pragma unroll
            for (int j = 0; j < 4; j++) { DOT4(a[i * 4 + j], wv[i], iv[j]) }
        }
    }
    float* rb = &G.red[(kc * 16 + tile) * RWS];
    #pragma unroll
    for (int q = 0; q < 20; q++) rb[q] = a[q];
}

__global__ void __launch_bounds__(NTHR, 1) ntm_kernel(
    const float* __restrict__ x,    const float* __restrict__ h0,
    const float* __restrict__ c0,   const float* __restrict__ mem0,
    const float* __restrict__ r0_,  const float* __restrict__ W_ih,
    const float* __restrict__ b_ih, const float* __restrict__ W_hh,
    const float* __restrict__ b_hh, const float* __restrict__ W_fc,
    const float* __restrict__ b_fc, const float* __restrict__ W_e,
    const float* __restrict__ b_e,  const float* __restrict__ W_a,
    const float* __restrict__ b_a,  const float* __restrict__ W_k,
    const float* __restrict__ b_k,  const float* __restrict__ W_b,
    const float* __restrict__ b_b,  float* __restrict__ out)
{
    extern __shared__ unsigned char smem_raw[];
    Smem& s = *reinterpret_cast<Smem*>(smem_raw);
    const int cta = blockIdx.x;
    const int tid = threadIdx.x;
    const int lane = tid & 31, wrp = tid >> 5;

    float* out_O = out;
    float* out_h = out + (size_t)BB * TT * OUTD;
    float* out_c = out_h + BB * HHD;

    if (tid == 0) s.genv = ld_acq(&g_gen);

    const bool is_mem = (cta < NMEM);
    const int gi = cta - NMEM;
    const int cnt   = (gi < 64) ? 5 : 4;
    const int hbase = (gi < 64) ? gi * 5 : 320 + (gi - 64) * 4;

    // ---------------- init ----------------
    if (!is_mem) {
        GemmS& G = s.u.g;
        for (int idx = tid; idx < RWS * KPAD; idx += NTHR) {
            int lr = idx / KPAD, k = idx - lr * KPAD;
            int g = lr & 3, hl = lr >> 2;
            float v = 0.f;
            if (hl < cnt) {
                int gr = g * HHD + hbase + hl;
                if (k < IND)             v = W_ih[gr * (IND + MMD) + k];
                else if (k < IND + HHD)  v = W_hh[gr * HHD + (k - IND)];
                else if (k < KTOT)       v = W_ih[gr * (IND + MMD) + IND + (k - IND - HHD)];
            }
            G.W[idx] = v;
        }
        if (tid < RWS) {
            int g = tid & 3, hl = tid >> 2;
            G.bias[tid] = (hl < cnt)
                ? (b_ih[g * HHD + hbase + hl] + b_hh[g * HHD + hbase + hl]) : 0.f;
        }
        if (tid < 5 * BB) {
            int b = tid / 5, hl = tid - b * 5;
            G.cst[hl * BB + b] = (hl < cnt) ? c0[b * HHD + hbase + hl] : 0.f;
        }
        for (int idx = tid; idx < BB * KPAD; idx += NTHR) {
            int b = idx / KPAD, k = idx - b * KPAD;
            float v = 0.f;
            if (k < IND)             v = x[(b * TT) * IND + k];
            else if (k < IND + HHD)  v = h0[b * HHD + (k - IND)];
            G.inp[idx] = v;
        }
        __syncthreads();
        gemm_xh(G, tid);               // xh partials for t = 0
    } else {
        MemS& M = s.u.m;
        for (int idx = tid; idx < RCACHE * HHD; idx += NTHR) {
            int r = idx >> 9, k = idx & (HHD - 1);
            M.pw[idx] = prow(r, W_k, W_b, W_e, W_a)[k];
        }
        for (int idx = tid; idx < NND * MMD; idx += NTHR) {
            int n = idx / MMD, m = idx - n * MMD;
            M.mem[n * 41 + m] = mem0[cta * NND * MMD + idx];
        }
        // seed r(-1) into the buffer part1(t=0) will read (hp^1 at t=0 -> [1])
        if (tid < MMD) g_r[1][cta][tid] = r0_[cta * MMD + tid];
    }
    __syncthreads();
    const unsigned gen = s.genv;
    const unsigned hb0 = gen * (unsigned)TT;        // h-flag base this launch
    const unsigned rb0 = gen * (unsigned)(TT - 1);  // r-flag base this launch

    if (is_mem) {
        // =================== memory CTA loop (R7 verbatim, __expf swap) ===================
        MemS& M = s.u.m;
        const int b = cta;
        for (int t = 0; t < TT - 1; t++) {
            const int hp = t & 1;
            wait_hflags(hb0 + (unsigned)(t + 1));
            {   // 121-row projection GEMV over h(t)
                const float4* h4 = reinterpret_cast<const float4*>(&g_h[hp][b][0]);
                float4 hv0 = __ldcg(h4 + lane);
                float4 hv1 = __ldcg(h4 + lane + 32);
                float4 hv2 = __ldcg(h4 + lane + 64);
                float4 hv3 = __ldcg(h4 + lane + 96);
                #pragma unroll
                for (int jr = 0; jr < 8; jr++) {
                    int r = wrp + 16 * jr;
                    if (r <= 120) {
                        float4 a0, a1, a2, a3;
                        if (r < RCACHE) {
                            const float4* w4 =
                                reinterpret_cast<const float4*>(&M.pw[r * HHD]);
                            a0 = w4[lane];      a1 = w4[lane + 32];
                            a2 = w4[lane + 64]; a3 = w4[lane + 96];
                        } else {
                            const float4* w4 = reinterpret_cast<const float4*>(
                                prow(r, W_k, W_b, W_e, W_a));
                            a0 = __ldg(w4 + lane);      a1 = __ldg(w4 + lane + 32);
                            a2 = __ldg(w4 + lane + 64); a3 = __ldg(w4 + lane + 96);
                        }
                        float acc = 0.f;
                        DOT4(acc, a0, hv0) DOT4(acc, a1, hv1)
                        DOT4(acc, a2, hv2) DOT4(acc, a3, hv3)
                        #pragma unroll
                        for (int off = 16; off; off >>= 1)
                            acc += __shfl_xor_sync(0xffffffffu, acc, off);
                        if (lane == 0) M.proj[r] = acc;
                    }
                }
            }
            __syncthreads();
            if (tid < 121) {
                float v = M.proj[tid];
                if (tid < 40) {
                    M.key[tid] = tanhf(v + b_k[tid]);
                } else if (tid == 40) {
                    float zz = v + b_b[0];
                    M.scal[1] = fmaxf(zz, 0.f) + log1pf(__expf(-fabsf(zz))) + EPSV;
                } else if (tid <= 80) {
                    int m = tid - 41;
                    M.ev[m] = 1.f / (1.f + __expf(-(v + b_e[m])));
                } else {
                    int m = tid - 81;
                    M.av[m] = tanhf(v + b_a[m]);
                }
            }
            __syncthreads();
            if (tid < NND) {
                const float* mr = &M.mem[tid * 41];
                float dot = 0.f, nrm = 0.f;
                #pragma unroll
                for (int m = 0; m < MMD; m++) {
                    float mv = mr[m];
                    dot += mv * M.key[m];
                    nrm += mv * mv;
                }
                M.z[tid] = dot / (sqrtf(nrm) + EPSV);
            } else if (wrp == 8) {
                float v = 0.f;
                if (lane < MMD)      { float kv = M.key[lane];      v  = kv * kv; }
                if (lane + 32 < MMD) { float kv = M.key[lane + 32]; v += kv * kv; }
                #pragma unroll
                for (int off = 16; off; off >>= 1)
                    v += __shfl_xor_sync(0xffffffffu, v, off);
                if (lane == 0) M.scal[0] = sqrtf(v) + EPSV;
            }
            __syncthreads();
            if (wrp == 0) {            // softmax, one warp
                float bscale = M.scal[1] / M.scal[0];
                float z0 = M.z[lane]      * bscale;
                float z1 = M.z[lane + 32] * bscale;
                float z2 = M.z[lane + 64] * bscale;
                float z3 = M.z[lane + 96] * bscale;
                float mx = fmaxf(fmaxf(z0, z1), fmaxf(z2, z3));
                #pragma unroll
                for (int off = 16; off; off >>= 1)
                    mx = fmaxf(mx, __shfl_xor_sync(0xffffffffu, mx, off));
                float e0 = __expf(z0 - mx), e1 = __expf(z1 - mx);
                float e2 = __expf(z2 - mx), e3 = __expf(z3 - mx);
                float sv = e0 + e1 + e2 + e3;
                #pragma unroll
                for (int off = 16; off; off >>= 1)
                    sv += __shfl_xor_sync(0xffffffffu, sv, off);
                float inv = 1.f / sv;
                M.wsm[lane]      = e0 * inv;
                M.wsm[lane + 32] = e1 * inv;
                M.wsm[lane + 64] = e2 * inv;
                M.wsm[lane + 96] = e3 * inv;
            }
            __syncthreads();
            if (tid < NND) {           // erase/add
                float wv = M.wsm[tid];
                float* mr = &M.mem[tid * 41];
                #pragma unroll
                for (int m = 0; m < MMD; m++)
                    mr[m] = mr[m] * (1.f - wv * M.ev[m]) + wv * M.av[m];
            }
            __syncthreads();
            if (tid < 320) {           // read r = w^T M, partials
                int m = tid >> 3, p = tid & 7;
                float sv = 0.f;
                #pragma unroll
                for (int n = p * 16; n < p * 16 + 16; n++)
                    sv += M.wsm[n] * M.mem[n * 41 + m];
                M.rred[tid] = sv;
            }
            __syncthreads();
            if (tid < MMD) {
                float sv = 0.f;
                #pragma unroll
                for (int p = 0; p < 8; p++) sv += M.rred[tid * 8 + p];
                g_r[hp][b][tid] = sv;
            }
            __syncthreads();
            if (tid == 0) {
                st_rel(&g_rflags[cta * 32], rb0 + (unsigned)(t + 1));
            }
        }
    } else {
        // =================== gemm CTA loop ===================
        GemmS& G = s.u.g;
        for (int t = 0; t < TT; t++) {
            const int hp = t & 1;
            // ---- part 1: finish gates with r(t-1) -> h(t) ----
            if (t > 0) {
                if (wrp == 0) {
                    unsigned tgt = rb0 + (unsigned)t;
                    for (;;) {
                        bool ok = true;
                        if (lane < NMEM)
                            ok = ((int)(ld_acq(&g_rflags[lane * 32]) - tgt) >= 0);
                        if (__all_sync(0xffffffffu, ok)) break;
                    }
                }
                __syncthreads();
            }
            if (tid < 64) {            // r-part folded; r read direct from L2
                const int kc = tid >> 4, tile = tid & 15;
                const int rg = tile & 3, bg = tile >> 2;
                const int q0 = (kc < 2) ? kc * 3 : 6 + (kc - 2) * 2;
                const int rlen = (kc < 2) ? 3 : 2;
                const float4* W4 = reinterpret_cast<const float4*>(G.W);
                const float4* R4 =
                    reinterpret_cast<const float4*>(&g_r[hp ^ 1][0][0]);
                float4 iv[4][3];
                #pragma unroll 3
                for (int q = 0; q < rlen; q++) {
                    #pragma unroll
                    for (int j = 0; j < 4; j++)
                        iv[j][q] = __ldcg(R4 + (bg + 4 * j) * 10 + q0 + q);
                }
                float a[20];
                float* rb = &G.red[(kc * 16 + tile) * RWS];
                #pragma unroll
                for (int q = 0; q < 20; q++) a[q] = rb[q];
                #pragma unroll 3
                for (int q = 0; q < rlen; q++) {
                    float4 wv[5];
                    #pragma unroll
                    for (int i = 0; i < 5; i++)
                        wv[i] = W4[(rg + 4 * i) * KP4 + 144 + q0 + q];
                    #pragma unroll
                    for (int i = 0; i < 5; i++) {
                        #pragma unroll
                        for (int j = 0; j < 4; j++) { DOT4(a[i * 4 + j], wv[i], iv[j][q]) }
                    }
                }
                #pragma unroll
                for (int q = 0; q < 20; q++) rb[q] = a[q];
            }
            __syncthreads();
            if (tid < RWS * BB) {      // reduce split-K
                int b = tid / RWS, lr = tid - b * RWS;
                int tile = (b & 3) * 4 + (lr & 3);
                int cell = (lr >> 2) * 4 + (b >> 2);
                float v = G.bias[lr];
                #pragma unroll
                for (int kc2 = 0; kc2 < 32; kc2++)
                    v += G.red[(kc2 * 16 + tile) * RWS + cell];
                G.gate[lr * BB + b] = v;
            }
            __syncthreads();
            if (tid < 5 * BB) {        // LSTM pointwise -> h(t)
                int b = tid / 5, hl = tid - b * 5;
                if (hl < cnt) {
                    float gv_i = G.gate[(0 + 4 * hl) * BB + b];
                    float gv_f = G.gate[(1 + 4 * hl) * BB + b];
                    float gv_g = G.gate[(2 + 4 * hl) * BB + b];
                    float gv_o = G.gate[(3 + 4 * hl) * BB + b];
                    float iv = 1.f / (1.f + __expf(-gv_i));
                    float fv = 1.f / (1.f + __expf(-gv_f));
                    float gv = tanhf(gv_g);
                    float ov = 1.f / (1.f + __expf(-gv_o));
                    float cn = fv * G.cst[hl * BB + b] + iv * gv;
                    float hn = ov * tanhf(cn);
                    G.cst[hl * BB + b] = cn;
                    g_h[hp][b][hbase + hl] = hn;
                    if (t == TT - 1) {
                        out_h[b * HHD + hbase + hl] = hn;
                        out_c[b * HHD + hbase + hl] = cn;
                    }
                }
            }
            __syncthreads();
            if (tid == 0) {
                st_rel(&g_hflags[gi * 32], hb0 + (unsigned)(t + 1));
            }
            // ---- window B: prestage, fc(t), xh-gemm for t+1 ----
            wait_hflags(hb0 + (unsigned)(t + 1));
            for (int idx = tid; idx < BB * 144; idx += NTHR) {
                int b = idx / 144, q = idx - b * 144;
                float4 v;
                if (q < 16) {
                    v = (t + 1 < TT)
                        ? __ldg(reinterpret_cast<const float4*>(
                              &x[(b * TT + t + 1) * IND]) + q)
                        : make_float4(0.f, 0.f, 0.f, 0.f);
                } else {
                    v = __ldcg(reinterpret_cast<const float4*>(&g_h[hp][b][0])
                               + (q - 16));
                }
                reinterpret_cast<float4*>(G.inp)[b * KP4 + q] = v;
            }
            __syncthreads();
            {   // fc(t) from staged h
                int grp = tid >> 4, l16 = tid & 15;
                int d = gi + NGEMM * grp;
                bool valid = (d < 1024);
                int d2 = valid ? d : 0;
                int b = d2 >> 6, row = d2 & 63;
                const float4* w4 =
                    reinterpret_cast<const float4*>(W_fc + row * HHD);
                const float4* h4 =
                    reinterpret_cast<const float4*>(G.inp) + b * KP4 + 16;
                float acc = 0.f;
                #pragma unroll
                for (int q = 0; q < 8; q++) {
                    float4 wv = __ldg(w4 + l16 + 16 * q);
                    float4 hv = h4[l16 + 16 * q];
                    DOT4(acc, wv, hv)
                }
                #pragma unroll
                for (int off = 8; off; off >>= 1)
                    acc += __shfl_xor_sync(0xffffffffu, acc, off);
                if (valid && l16 == 0)
                    out_O[(b * TT + t) * OUTD + row] = tanhf(acc + b_fc[row]);
            }
            if (t + 1 < TT) gemm_xh(G, tid);
        }
        if (cta == NCTA - 1 && tid == 0) {
            st_rel(&g_gen, gen + 1);   // next launch's flag base
        }
    }
}

extern "C" void kernel_launch(void* const* d_in, const int* in_sizes, int n_in,
                              void* d_out, int out_size) {
    (void)in_sizes; (void)n_in; (void)out_size;
    cudaFuncSetAttribute(ntm_kernel,
                         cudaFuncAttributeMaxDynamicSharedMemorySize,
                         (int)sizeof(Smem));
    ntm_kernel<<<NCTA, NTHR, sizeof(Smem)>>>(
        (const float*)d_in[0],  (const float*)d_in[1],  (const float*)d_in[2],
        (const float*)d_in[3],  (const float*)d_in[4],  (const float*)d_in[5],
        (const float*)d_in[6],  (const float*)d_in[7],  (const float*)d_in[8],
        (const float*)d_in[9],  (const float*)d_in[10], (const float*)d_in[11],
        (const float*)d_in[12], (const float*)d_in[13], (const float*)d_in[14],
        (const float*)d_in[15], (const float*)d_in[16], (const float*)d_in[17],
        (const float*)d_in[18], (float*)d_out);
}

// round 15
// speedup vs baseline: 1.5091x; 1.5091x over previous
#include <cuda_runtime.h>
#include <math.h>

#define BB 16
#define TT 1024
#define IND 64
#define OUTD 64
#define HHD 512
#define NND 128
#define MMD 40
#define KTOT 616        // IND + HHD + MMD, order [x|h|r]
#define KP4  157        // padded row stride in float4
#define KPAD 628
#define NCTA 128
#define NMEM 16
#define NGEMM 112
#define NTHR 512
#define RWS 20          // gate rows per gemm CTA
#define EPSV 1e-8f
#define RCACHE 80       // projection rows cached in smem (of 121)

// ---------------- persistent global state ----------------
__device__ __align__(16) float g_h[2][BB][HHD];
__device__ __align__(16) float g_r[2][BB][MMD];
__device__ unsigned g_hflags[NGEMM * 32];  // h(t)-ready, one per gemm CTA
__device__ unsigned g_rflags[NMEM * 32];   // r(t)-ready, one per mem CTA
__device__ unsigned g_gen = 0;             // launch generation

static __device__ __forceinline__ unsigned ld_acq(const unsigned* p) {
    unsigned v;
    asm volatile("ld.acquire.gpu.global.u32 %0, [%1];" : "=r"(v) : "l"(p) : "memory");
    return v;
}
static __device__ __forceinline__ void st_rel(unsigned* p, unsigned v) {
    asm volatile("st.release.gpu.global.u32 [%0], %1;" :: "l"(p), "r"(v) : "memory");
}

// Wait until all NGEMM h-flags >= k. Warp 0 polls, then CTA-wide sync.
static __device__ __forceinline__ void wait_hflags(unsigned k) {
    if (threadIdx.x < 32) {
        for (;;) {
            bool ok = true;
            #pragma unroll
            for (int q = 0; q < 4; q++) {
                int f = threadIdx.x + 32 * q;
                if (f < NGEMM)
                    ok &= ((int)(ld_acq(&g_hflags[f * 32]) - k) >= 0);
            }
            if (__all_sync(0xffffffffu, ok)) break;
        }
    }
    __syncthreads();
}

struct __align__(16) GemmS {
    alignas(16) float W[RWS * KPAD];       // gate-weight slice [x|h|r]
    alignas(16) float inp[BB * KPAD];      // staged [x|h|r]
    alignas(16) float red[32 * 16 * RWS];  // split-K partials
    float gate[RWS * BB];
    float bias[RWS];
    float cst[5 * BB];
};
struct __align__(16) MemS {
    alignas(16) float pw[RCACHE * HHD];    // projection weight rows
    float mem[NND * 41];
    float rred[320];
    float proj[NND];
    float key[MMD];
    float ev[MMD];
    float av[MMD];
    float z[NND];
    float wsm[NND];
    float scal[4];                         // [0]=||key||+eps, [1]=beta
};
struct __align__(16) Smem {
    union { GemmS g; MemS m; } u;
    unsigned genv;
};

static __device__ __forceinline__ const float* prow(int r,
    const float* W_k, const float* W_b, const float* W_e, const float* W_a)
{
    if (r < 40)  return W_k + r * HHD;
    if (r == 40) return W_b;
    if (r <= 80) return W_e + (r - 41) * HHD;
    return W_a + (r - 81) * HHD;
}

#define DOT4(acc, wv, iv) \
    acc += wv.x*iv.x; acc += wv.y*iv.y; acc += wv.z*iv.z; acc += wv.w*iv.w;

// xh-part GEMM (576 dims = f4 0..143), conflict-free interleaved mapping.
static __device__ __forceinline__ void gemm_xh(GemmS& G, int tid) {
    const int kc = tid >> 4, tile = tid & 15;
    const int rg = tile & 3, bg = tile >> 2;
    const int koff = (kc < 16) ? kc * 5 : 80 + (kc - 16) * 4;
    const int klen = (kc < 16) ? 5 : 4;
    const float4* W4 = reinterpret_cast<const float4*>(G.W);
    const float4* I4 = reinterpret_cast<const float4*>(G.inp);
    float a[20];
    #pragma unroll
    for (int q = 0; q < 20; q++) a[q] = 0.f;
    #pragma unroll 5
    for (int q = 0; q < klen; q++) {
        float4 wv[5], iv[4];
        #pragma unroll
        for (int i = 0; i < 5; i++) wv[i] = W4[(rg + 4 * i) * KP4 + koff + q];
        #pragma unroll
        for (int j = 0; j < 4; j++) iv[j] = I4[(bg + 4 * j) * KP4 + koff + q];
        #pragma unroll
        for (int i = 0; i < 5; i++) {
            #pragma unroll
            for (int j = 0; j < 4; j++) { DOT4(a[i * 4 + j], wv[i], iv[j]) }
        }
    }
    float* rb = &G.red[(kc * 16 + tile) * RWS];
    #pragma unroll
    for (int q = 0; q < 20; q++) rb[q] = a[q];
}

__global__ void __launch_bounds__(NTHR, 1) ntm_kernel(
    const float* __restrict__ x,    const float* __restrict__ h0,
    const float* __restrict__ c0,   const float* __restrict__ mem0,
    const float* __restrict__ r0_,  const float* __restrict__ W_ih,
    const float* __restrict__ b_ih, const float* __restrict__ W_hh,
    const float* __restrict__ b_hh, const float* __restrict__ W_fc,
    const float* __restrict__ b_fc, const float* __restrict__ W_e,
    const float* __restrict__ b_e,  const float* __restrict__ W_a,
    const float* __restrict__ b_a,  const float* __restrict__ W_k,
    const float* __restrict__ b_k,  const float* __restrict__ W_b,
    const float* __restrict__ b_b,  float* __restrict__ out)
{
    extern __shared__ unsigned char smem_raw[];
    Smem& s = *reinterpret_cast<Smem*>(smem_raw);
    const int cta = blockIdx.x;
    const int tid = threadIdx.x;
    const int lane = tid & 31, wrp = tid >> 5;

    float* out_O = out;
    float* out_h = out + (size_t)BB * TT * OUTD;
    float* out_c = out_h + BB * HHD;

    if (tid == 0) s.genv = ld_acq(&g_gen);

    const bool is_mem = (cta < NMEM);
    const int gi = cta - NMEM;
    const int cnt   = (gi < 64) ? 5 : 4;
    const int hbase = (gi < 64) ? gi * 5 : 320 + (gi - 64) * 4;

    // ---------------- init ----------------
    if (!is_mem) {
        GemmS& G = s.u.g;
        for (int idx = tid; idx < RWS * KPAD; idx += NTHR) {
            int lr = idx / KPAD, k = idx - lr * KPAD;
            int g = lr & 3, hl = lr >> 2;
            float v = 0.f;
            if (hl < cnt) {
                int gr = g * HHD + hbase + hl;
                if (k < IND)             v = W_ih[gr * (IND + MMD) + k];
                else if (k < IND + HHD)  v = W_hh[gr * HHD + (k - IND)];
                else if (k < KTOT)       v = W_ih[gr * (IND + MMD) + IND + (k - IND - HHD)];
            }
            G.W[idx] = v;
        }
        if (tid < RWS) {
            int g = tid & 3, hl = tid >> 2;
            G.bias[tid] = (hl < cnt)
                ? (b_ih[g * HHD + hbase + hl] + b_hh[g * HHD + hbase + hl]) : 0.f;
        }
        if (tid < 5 * BB) {
            int b = tid / 5, hl = tid - b * 5;
            G.cst[hl * BB + b] = (hl < cnt) ? c0[b * HHD + hbase + hl] : 0.f;
        }
        for (int idx = tid; idx < BB * KPAD; idx += NTHR) {
            int b = idx / KPAD, k = idx - b * KPAD;
            float v = 0.f;
            if (k < IND)             v = x[(b * TT) * IND + k];
            else if (k < IND + HHD)  v = h0[b * HHD + (k - IND)];
            else if (k < KTOT)       v = r0_[b * MMD + (k - IND - HHD)];
            G.inp[idx] = v;
        }
        __syncthreads();
        gemm_xh(G, tid);               // xh partials for t = 0
    } else {
        MemS& M = s.u.m;
        for (int idx = tid; idx < RCACHE * HHD; idx += NTHR) {
            int r = idx >> 9, k = idx & (HHD - 1);
            M.pw[idx] = prow(r, W_k, W_b, W_e, W_a)[k];
        }
        for (int idx = tid; idx < NND * MMD; idx += NTHR) {
            int n = idx / MMD, m = idx - n * MMD;
            M.mem[n * 41 + m] = mem0[cta * NND * MMD + idx];
        }
    }
    __syncthreads();
    const unsigned gen = s.genv;
    const unsigned hb0 = gen * (unsigned)TT;        // h-flag base this launch
    const unsigned rb0 = gen * (unsigned)(TT - 1);  // r-flag base this launch

    if (is_mem) {
        // =================== memory CTA loop ===================
        MemS& M = s.u.m;
        const int b = cta;
        for (int t = 0; t < TT - 1; t++) {
            const int hp = t & 1;
            wait_hflags(hb0 + (unsigned)(t + 1));
            {   // 121-row projection GEMV over h(t)
                const float4* h4 = reinterpret_cast<const float4*>(&g_h[hp][b][0]);
                float4 hv0 = __ldcg(h4 + lane);
                float4 hv1 = __ldcg(h4 + lane + 32);
                float4 hv2 = __ldcg(h4 + lane + 64);
                float4 hv3 = __ldcg(h4 + lane + 96);
                #pragma unroll
                for (int jr = 0; jr < 8; jr++) {
                    int r = wrp + 16 * jr;
                    if (r <= 120) {                       // warp-uniform
                        float4 a0, a1, a2, a3;
                        if (r < RCACHE) {
                            const float4* w4 = reinterpret_cast<const float4*>(&M.pw[r * HHD]);
                            a0 = w4[lane]; a1 = w4[lane + 32];
                            a2 = w4[lane + 64]; a3 = w4[lane + 96];
                        } else {
                            const float4* w4 = reinterpret_cast<const float4*>(
                                prow(r, W_k, W_b, W_e, W_a));
                            a0 = __ldg(w4 + lane); a1 = __ldg(w4 + lane + 32);
                            a2 = __ldg(w4 + lane + 64); a3 = __ldg(w4 + lane + 96);
                        }
                        float acc = 0.f;
                        DOT4(acc, a0, hv0) DOT4(acc, a1, hv1)
                        DOT4(acc, a2, hv2) DOT4(acc, a3, hv3)
                        #pragma unroll
                        for (int off = 16; off; off >>= 1)
                            acc += __shfl_xor_sync(0xffffffffu, acc, off);
                        if (lane == 0) M.proj[r] = acc;
                    }
                }
            }
            __syncthreads();
            if (tid < 121) {
                float v = M.proj[tid];
                if (tid < 40) {
                    M.key[tid] = tanhf(v + b_k[tid]);
                } else if (tid == 40) {
                    float zz = v + b_b[0];
                    M.scal[1] = fmaxf(zz, 0.f) + log1pf(__expf(-fabsf(zz))) + EPSV;
                } else if (tid <= 80) {
                    int m = tid - 41;
                    M.ev[m] = 1.f / (1.f + __expf(-(v + b_e[m])));
                } else {
                    int m = tid - 81;
                    M.av[m] = tanhf(v + b_a[m]);
                }
            }
            __syncthreads();
            if (tid < NND) {
                const float* mr = &M.mem[tid * 41];
                float dot = 0.f, nrm = 0.f;
                #pragma unroll
                for (int m = 0; m < MMD; m++) {
                    float mv = mr[m];
                    dot += mv * M.key[m];
                    nrm += mv * mv;
                }
                M.z[tid] = dot / (sqrtf(nrm) + EPSV);
            } else if (wrp == 8) {
                float v = 0.f;
                if (lane < MMD)      { float kv = M.key[lane];      v  = kv * kv; }
                if (lane + 32 < MMD) { float kv = M.key[lane + 32]; v += kv * kv; }
                #pragma unroll
                for (int off = 16; off; off >>= 1)
                    v += __shfl_xor_sync(0xffffffffu, v, off);
                if (lane == 0) M.scal[0] = sqrtf(v) + EPSV;
            }
            __syncthreads();
            if (wrp == 0) {            // softmax, one warp
                float bscale = M.scal[1] / M.scal[0];
                float z0 = M.z[lane]      * bscale;
                float z1 = M.z[lane + 32] * bscale;
                float z2 = M.z[lane + 64] * bscale;
                float z3 = M.z[lane + 96] * bscale;
                float mx = fmaxf(fmaxf(z0, z1), fmaxf(z2, z3));
                #pragma unroll
                for (int off = 16; off; off >>= 1)
                    mx = fmaxf(mx, __shfl_xor_sync(0xffffffffu, mx, off));
                float e0 = __expf(z0 - mx), e1 = __expf(z1 - mx);
                float e2 = __expf(z2 - mx), e3 = __expf(z3 - mx);
                float sv = e0 + e1 + e2 + e3;
                #pragma unroll
                for (int off = 16; off; off >>= 1)
                    sv += __shfl_xor_sync(0xffffffffu, sv, off);
                float inv = 1.f / sv;
                M.wsm[lane]      = e0 * inv;
                M.wsm[lane + 32] = e1 * inv;
                M.wsm[lane + 64] = e2 * inv;
                M.wsm[lane + 96] = e3 * inv;
            }
            __syncthreads();
            if (tid < NND) {           // erase/add
                float wv = M.wsm[tid];
                float* mr = &M.mem[tid * 41];
                #pragma unroll
                for (int m = 0; m < MMD; m++)
                    mr[m] = mr[m] * (1.f - wv * M.ev[m]) + wv * M.av[m];
            }
            __syncthreads();
            if (tid < 320) {           // read r = w^T M, partials
                int m = tid >> 3, p = tid & 7;
                float sv = 0.f;
                #pragma unroll
                for (int n = p * 16; n < p * 16 + 16; n++)
                    sv += M.wsm[n] * M.mem[n * 41 + m];
                M.rred[tid] = sv;
            }
            __syncthreads();
            if (tid < MMD) {
                float sv = 0.f;
                #pragma unroll
                for (int p = 0; p < 8; p++) sv += M.rred[tid * 8 + p];
                g_r[hp][b][tid] = sv;
            }
            __syncthreads();
            if (tid == 0) {
                __threadfence();
                st_rel(&g_rflags[cta * 32], rb0 + (unsigned)(t + 1));
            }
        }
    } else {
        // =================== gemm CTA loop ===================
        GemmS& G = s.u.g;
        for (int t = 0; t < TT; t++) {
            const int hp = t & 1;
            // ---- part 1: finish gates with r(t-1) -> h(t) ----
            if (t > 0) {
                if (wrp == 0) {
                    unsigned tgt = rb0 + (unsigned)t;
                    for (;;) {
                        bool ok = true;
                        if (lane < NMEM)
                            ok = ((int)(ld_acq(&g_rflags[lane * 32]) - tgt) >= 0);
                        if (__all_sync(0xffffffffu, ok)) break;
                    }
                }
                __syncthreads();
                if (tid < 160) {       // stage r(t-1) into inp f4 slots 144..153
                    int b = tid / 10, q = tid - b * 10;
                    const float4* gr4 =
                        reinterpret_cast<const float4*>(&g_r[hp ^ 1][b][0]);
                    reinterpret_cast<float4*>(G.inp)[b * KP4 + 144 + q] =
                        __ldcg(gr4 + q);
                }
                __syncthreads();
            }
            if (tid < 64) {            // r-part (40 dims) folded into red
                const int kc = tid >> 4, tile = tid & 15;
                const int rg = tile & 3, bg = tile >> 2;
                const int roff = (kc < 2) ? 144 + kc * 3 : 150 + (kc - 2) * 2;
                const int rlen = (kc < 2) ? 3 : 2;
                const float4* W4 = reinterpret_cast<const float4*>(G.W);
                const float4* I4 = reinterpret_cast<const float4*>(G.inp);
                float a[20];
                float* rb = &G.red[(kc * 16 + tile) * RWS];
                #pragma unroll
                for (int q = 0; q < 20; q++) a[q] = rb[q];
                #pragma unroll 3
                for (int q = 0; q < rlen; q++) {
                    float4 wv[5], iv[4];
                    #pragma unroll
                    for (int i = 0; i < 5; i++)
                        wv[i] = W4[(rg + 4 * i) * KP4 + roff + q];
                    #pragma unroll
                    for (int j = 0; j < 4; j++)
                        iv[j] = I4[(bg + 4 * j) * KP4 + roff + q];
                    #pragma unroll
                    for (int i = 0; i < 5; i++) {
                        #pragma unroll
                        for (int j = 0; j < 4; j++) { DOT4(a[i * 4 + j], wv[i], iv[j]) }
                    }
                }
                #pragma unroll
                for (int q = 0; q < 20; q++) rb[q] = a[q];
            }
            __syncthreads();
            if (tid < RWS * BB) {      // reduce split-K
                int b = tid / RWS, lr = tid - b * RWS;
                int tile = (b & 3) * 4 + (lr & 3);
                int cell = (lr >> 2) * 4 + (b >> 2);
                float v = G.bias[lr];
                #pragma unroll
                for (int kc2 = 0; kc2 < 32; kc2++)
                    v += G.red[(kc2 * 16 + tile) * RWS + cell];
                G.gate[lr * BB + b] = v;
            }
            __syncthreads();
            if (tid < 5 * BB) {        // LSTM pointwise -> h(t)
                int b = tid / 5, hl = tid - b * 5;
                if (hl < cnt) {
                    float gv_i = G.gate[(0 + 4 * hl) * BB + b];
                    float gv_f = G.gate[(1 + 4 * hl) * BB + b];
                    float gv_g = G.gate[(2 + 4 * hl) * BB + b];
                    float gv_o = G.gate[(3 + 4 * hl) * BB + b];
                    float iv = 1.f / (1.f + __expf(-gv_i));
                    float fv = 1.f / (1.f + __expf(-gv_f));
                    float gv = tanhf(gv_g);
                    float ov = 1.f / (1.f + __expf(-gv_o));
                    float cn = fv * G.cst[hl * BB + b] + iv * gv;
                    float hn = ov * tanhf(cn);
                    G.cst[hl * BB + b] = cn;
                    g_h[hp][b][hbase + hl] = hn;
                    if (t == TT - 1) {
                        out_h[b * HHD + hbase + hl] = hn;
                        out_c[b * HHD + hbase + hl] = cn;
                    }
                }
            }
            __syncthreads();
            if (tid == 0) {
                __threadfence();
                st_rel(&g_hflags[gi * 32], hb0 + (unsigned)(t + 1));
            }
            // ---- window B: prestage, fc(t), xh-gemm for t+1 ----
            wait_hflags(hb0 + (unsigned)(t + 1));
            for (int idx = tid; idx < BB * 144; idx += NTHR) {
                int b = idx / 144, q = idx - b * 144;
                float4 v;
                if (q < 16) {
                    v = (t + 1 < TT)
                        ? __ldg(reinterpret_cast<const float4*>(
                              &x[(b * TT + t + 1) * IND]) + q)
                        : make_float4(0.f, 0.f, 0.f, 0.f);
                } else {
                    v = __ldcg(reinterpret_cast<const float4*>(&g_h[hp][b][0])
                               + (q - 16));
                }
                reinterpret_cast<float4*>(G.inp)[b * KP4 + q] = v;
            }
            __syncthreads();
            {   // fc(t) from staged h
                int grp = tid >> 4, l16 = tid & 15;
                int d = gi + NGEMM * grp;
                bool valid = (d < 1024);
                int d2 = valid ? d : 0;
                int b = d2 >> 6, row = d2 & 63;
                const float4* w4 =
                    reinterpret_cast<const float4*>(W_fc + row * HHD);
                const float4* h4 =
                    reinterpret_cast<const float4*>(G.inp) + b * KP4 + 16;
                float acc = 0.f;
                #pragma unroll
                for (int q = 0; q < 8; q++) {
                    float4 wv = __ldg(w4 + l16 + 16 * q);
                    float4 hv = h4[l16 + 16 * q];
                    DOT4(acc, wv, hv)
                }
                #pragma unroll
                for (int off = 8; off; off >>= 1)
                    acc += __shfl_xor_sync(0xffffffffu, acc, off);
                if (valid && l16 == 0)
                    out_O[(b * TT + t) * OUTD + row] = tanhf(acc + b_fc[row]);
            }
            if (t + 1 < TT) gemm_xh(G, tid);
        }
        if (cta == NCTA - 1 && tid == 0) {
            st_rel(&g_gen, gen + 1);   // next launch's flag base
        }
    }
}

extern "C" void kernel_launch(void* const* d_in, const int* in_sizes, int n_in,
                              void* d_out, int out_size) {
    (void)in_sizes; (void)n_in; (void)out_size;
    cudaFuncSetAttribute(ntm_kernel,
                         cudaFuncAttributeMaxDynamicSharedMemorySize,
                         (int)sizeof(Smem));
    ntm_kernel<<<NCTA, NTHR, sizeof(Smem)>>>(
        (const float*)d_in[0],  (const float*)d_in[1],  (const float*)d_in[2],
        (const float*)d_in[3],  (const float*)d_in[4],  (const float*)d_in[5],
        (const float*)d_in[6],  (const float*)d_in[7],  (const float*)d_in[8],
        (const float*)d_in[9],  (const float*)d_in[10], (const float*)d_in[11],
        (const float*)d_in[12], (const float*)d_in[13], (const float*)d_in[14],
        (const float*)d_in[15], (const float*)d_in[16], (const float*)d_in[17],
        (const float*)d_in[18], (float*)d_out);
}

// round 16
// speedup vs baseline: 1.5682x; 1.0392x over previous
#include <cuda_runtime.h>
#include <math.h>

#define BB 16
#define TT 1024
#define IND 64
#define OUTD 64
#define HHD 512
#define NND 128
#define MMD 40
#define KTOT 616        // IND + HHD + MMD, order [x|h|r]
#define KP4  157        // padded row stride in float4
#define KPAD 628
#define NCTA 128
#define NMEM 16
#define NGEMM 112
#define NTHR 512
#define RWS 20          // gate rows per gemm CTA
#define EPSV 1e-8f
#define RCACHE 80       // projection rows cached in smem (of 121)

// ---------------- persistent global state ----------------
__device__ __align__(16) float g_h[2][BB][HHD];
__device__ __align__(16) float g_r[2][BB][MMD];
__device__ unsigned g_hflags[NGEMM * 32];  // h(t)-ready, one per gemm CTA
__device__ unsigned g_rflags[NMEM * 32];   // r(t)-ready, one per mem CTA
__device__ unsigned g_gen = 0;             // launch generation

static __device__ __forceinline__ unsigned ld_acq(const unsigned* p) {
    unsigned v;
    asm volatile("ld.acquire.gpu.global.u32 %0, [%1];" : "=r"(v) : "l"(p) : "memory");
    return v;
}
static __device__ __forceinline__ void st_rel(unsigned* p, unsigned v) {
    asm volatile("st.release.gpu.global.u32 [%0], %1;" :: "l"(p), "r"(v) : "memory");
}

// Wait until all NGEMM h-flags >= k. Warp 0 polls, then CTA-wide sync.
static __device__ __forceinline__ void wait_hflags(unsigned k) {
    if (threadIdx.x < 32) {
        for (;;) {
            bool ok = true;
            #pragma unroll
            for (int q = 0; q < 4; q++) {
                int f = threadIdx.x + 32 * q;
                if (f < NGEMM)
                    ok &= ((int)(ld_acq(&g_hflags[f * 32]) - k) >= 0);
            }
            if (__all_sync(0xffffffffu, ok)) break;
        }
    }
    __syncthreads();
}

struct __align__(16) GemmS {
    alignas(16) float W[RWS * KPAD];       // gate-weight slice [x|h|r]
    alignas(16) float inp[BB * KPAD];      // staged [x|h|r]
    alignas(16) float red[32 * 16 * RWS];  // split-K partials
    float gate[RWS * BB];
    float bias[RWS];
    float cst[5 * BB];
};
struct __align__(16) MemS {
    alignas(16) float pw[RCACHE * HHD];    // projection weight rows
    float mem[NND * 41];
    float rred[320];
    float proj[NND];
    float key[MMD];
    float ev[MMD];
    float av[MMD];
    float z[NND];
    float wsm[NND];
    float scal[4];                         // [0]=||key||+eps, [1]=beta
};
struct __align__(16) Smem {
    union { GemmS g; MemS m; } u;
    unsigned genv;
};

static __device__ __forceinline__ const float* prow(int r,
    const float* W_k, const float* W_b, const float* W_e, const float* W_a)
{
    if (r < 40)  return W_k + r * HHD;
    if (r == 40) return W_b;
    if (r <= 80) return W_e + (r - 41) * HHD;
    return W_a + (r - 81) * HHD;
}

#define DOT4(acc, wv, iv) \
    acc += wv.x*iv.x; acc += wv.y*iv.y; acc += wv.z*iv.z; acc += wv.w*iv.w;

// xh-part GEMM (576 dims = f4 0..143), conflict-free interleaved mapping.
static __device__ __forceinline__ void gemm_xh(GemmS& G, int tid) {
    const int kc = tid >> 4, tile = tid & 15;
    const int rg = tile & 3, bg = tile >> 2;
    const int koff = (kc < 16) ? kc * 5 : 80 + (kc - 16) * 4;
    const int klen = (kc < 16) ? 5 : 4;
    const float4* W4 = reinterpret_cast<const float4*>(G.W);
    const float4* I4 = reinterpret_cast<const float4*>(G.inp);
    float a[20];
    #pragma unroll
    for (int q = 0; q < 20; q++) a[q] = 0.f;
    #pragma unroll 5
    for (int q = 0; q < klen; q++) {
        float4 wv[5], iv[4];
        #pragma unroll
        for (int i = 0; i < 5; i++) wv[i] = W4[(rg + 4 * i) * KP4 + koff + q];
        #pragma unroll
        for (int j = 0; j < 4; j++) iv[j] = I4[(bg + 4 * j) * KP4 + koff + q];
        #pragma unroll
        for (int i = 0; i < 5; i++) {
            #pragma unroll
            for (int j = 0; j < 4; j++) { DOT4(a[i * 4 + j], wv[i], iv[j]) }
        }
    }
    float* rb = &G.red[(kc * 16 + tile) * RWS];
    #pragma unroll
    for (int q = 0; q < 20; q++) rb[q] = a[q];
}

__global__ void __launch_bounds__(NTHR, 1) ntm_kernel(
    const float* __restrict__ x,    const float* __restrict__ h0,
    const float* __restrict__ c0,   const float* __restrict__ mem0,
    const float* __restrict__ r0_,  const float* __restrict__ W_ih,
    const float* __restrict__ b_ih, const float* __restrict__ W_hh,
    const float* __restrict__ b_hh, const float* __restrict__ W_fc,
    const float* __restrict__ b_fc, const float* __restrict__ W_e,
    const float* __restrict__ b_e,  const float* __restrict__ W_a,
    const float* __restrict__ b_a,  const float* __restrict__ W_k,
    const float* __restrict__ b_k,  const float* __restrict__ W_b,
    const float* __restrict__ b_b,  float* __restrict__ out)
{
    extern __shared__ unsigned char smem_raw[];
    Smem& s = *reinterpret_cast<Smem*>(smem_raw);
    const int cta = blockIdx.x;
    const int tid = threadIdx.x;
    const int lane = tid & 31, wrp = tid >> 5;

    float* out_O = out;
    float* out_h = out + (size_t)BB * TT * OUTD;
    float* out_c = out_h + BB * HHD;

    if (tid == 0) s.genv = ld_acq(&g_gen);

    const bool is_mem = (cta < NMEM);
    const int gi = cta - NMEM;
    const int cnt   = (gi < 64) ? 5 : 4;
    const int hbase = (gi < 64) ? gi * 5 : 320 + (gi - 64) * 4;

    // ---------------- init ----------------
    if (!is_mem) {
        GemmS& G = s.u.g;
        for (int idx = tid; idx < RWS * KPAD; idx += NTHR) {
            int lr = idx / KPAD, k = idx - lr * KPAD;
            int g = lr & 3, hl = lr >> 2;
            float v = 0.f;
            if (hl < cnt) {
                int gr = g * HHD + hbase + hl;
                if (k < IND)             v = W_ih[gr * (IND + MMD) + k];
                else if (k < IND + HHD)  v = W_hh[gr * HHD + (k - IND)];
                else if (k < KTOT)       v = W_ih[gr * (IND + MMD) + IND + (k - IND - HHD)];
            }
            G.W[idx] = v;
        }
        if (tid < RWS) {
            int g = tid & 3, hl = tid >> 2;
            G.bias[tid] = (hl < cnt)
                ? (b_ih[g * HHD + hbase + hl] + b_hh[g * HHD + hbase + hl]) : 0.f;
        }
        if (tid < 5 * BB) {
            int b = tid / 5, hl = tid - b * 5;
            G.cst[hl * BB + b] = (hl < cnt) ? c0[b * HHD + hbase + hl] : 0.f;
        }
        for (int idx = tid; idx < BB * KPAD; idx += NTHR) {
            int b = idx / KPAD, k = idx - b * KPAD;
            float v = 0.f;
            if (k < IND)             v = x[(b * TT) * IND + k];
            else if (k < IND + HHD)  v = h0[b * HHD + (k - IND)];
            else if (k < KTOT)       v = r0_[b * MMD + (k - IND - HHD)];
            G.inp[idx] = v;
        }
        __syncthreads();
        gemm_xh(G, tid);               // xh partials for t = 0
    } else {
        MemS& M = s.u.m;
        for (int idx = tid; idx < RCACHE * HHD; idx += NTHR) {
            int r = idx >> 9, k = idx & (HHD - 1);
            M.pw[idx] = prow(r, W_k, W_b, W_e, W_a)[k];
        }
        for (int idx = tid; idx < NND * MMD; idx += NTHR) {
            int n = idx / MMD, m = idx - n * MMD;
            M.mem[n * 41 + m] = mem0[cta * NND * MMD + idx];
        }
    }
    __syncthreads();
    const unsigned gen = s.genv;
    const unsigned hb0 = gen * (unsigned)TT;        // h-flag base this launch
    const unsigned rb0 = gen * (unsigned)(TT - 1);  // r-flag base this launch

    if (is_mem) {
        // =================== memory CTA loop ===================
        MemS& M = s.u.m;
        const int b = cta;
        for (int t = 0; t < TT - 1; t++) {
            const int hp = t & 1;
            wait_hflags(hb0 + (unsigned)(t + 1));
            {   // 121-row projection GEMV over h(t)
                const float4* h4 = reinterpret_cast<const float4*>(&g_h[hp][b][0]);
                float4 hv0 = __ldcg(h4 + lane);
                float4 hv1 = __ldcg(h4 + lane + 32);
                float4 hv2 = __ldcg(h4 + lane + 64);
                float4 hv3 = __ldcg(h4 + lane + 96);
                #pragma unroll
                for (int jr = 0; jr < 8; jr++) {
                    int r = wrp + 16 * jr;
                    if (r <= 120) {                       // warp-uniform
                        float4 a0, a1, a2, a3;
                        if (r < RCACHE) {
                            const float4* w4 = reinterpret_cast<const float4*>(&M.pw[r * HHD]);
                            a0 = w4[lane]; a1 = w4[lane + 32];
                            a2 = w4[lane + 64]; a3 = w4[lane + 96];
                        } else {
                            const float4* w4 = reinterpret_cast<const float4*>(
                                prow(r, W_k, W_b, W_e, W_a));
                            a0 = __ldg(w4 + lane); a1 = __ldg(w4 + lane + 32);
                            a2 = __ldg(w4 + lane + 64); a3 = __ldg(w4 + lane + 96);
                        }
                        float acc = 0.f;
                        DOT4(acc, a0, hv0) DOT4(acc, a1, hv1)
                        DOT4(acc, a2, hv2) DOT4(acc, a3, hv3)
                        #pragma unroll
                        for (int off = 16; off; off >>= 1)
                            acc += __shfl_xor_sync(0xffffffffu, acc, off);
                        if (lane == 0) M.proj[r] = acc;
                    }
                }
            }
            __syncthreads();
            if (tid < 121) {
                float v = M.proj[tid];
                if (tid < 40) {
                    M.key[tid] = tanhf(v + b_k[tid]);
                } else if (tid == 40) {
                    float zz = v + b_b[0];
                    M.scal[1] = fmaxf(zz, 0.f) + log1pf(expf(-fabsf(zz))) + EPSV;
                } else if (tid <= 80) {
                    int m = tid - 41;
                    M.ev[m] = 1.f / (1.f + expf(-(v + b_e[m])));
                } else {
                    int m = tid - 81;
                    M.av[m] = tanhf(v + b_a[m]);
                }
            }
            __syncthreads();
            if (tid < NND) {
                const float* mr = &M.mem[tid * 41];
                float dot = 0.f, nrm = 0.f;
                #pragma unroll
                for (int m = 0; m < MMD; m++) {
                    float mv = mr[m];
                    dot += mv * M.key[m];
                    nrm += mv * mv;
                }
                M.z[tid] = dot / (sqrtf(nrm) + EPSV);
            } else if (wrp == 8) {
                float v = 0.f;
                if (lane < MMD)      { float kv = M.key[lane];      v  = kv * kv; }
                if (lane + 32 < MMD) { float kv = M.key[lane + 32]; v += kv * kv; }
                #pragma unroll
                for (int off = 16; off; off >>= 1)
                    v += __shfl_xor_sync(0xffffffffu, v, off);
                if (lane == 0) M.scal[0] = sqrtf(v) + EPSV;
            }
            __syncthreads();
            if (wrp == 0) {            // softmax, one warp
                float bscale = M.scal[1] / M.scal[0];
                float z0 = M.z[lane]      * bscale;
                float z1 = M.z[lane + 32] * bscale;
                float z2 = M.z[lane + 64] * bscale;
                float z3 = M.z[lane + 96] * bscale;
                float mx = fmaxf(fmaxf(z0, z1), fmaxf(z2, z3));
                #pragma unroll
                for (int off = 16; off; off >>= 1)
                    mx = fmaxf(mx, __shfl_xor_sync(0xffffffffu, mx, off));
                float e0 = expf(z0 - mx), e1 = expf(z1 - mx);
                float e2 = expf(z2 - mx), e3 = expf(z3 - mx);
                float sv = e0 + e1 + e2 + e3;
                #pragma unroll
                for (int off = 16; off; off >>= 1)
                    sv += __shfl_xor_sync(0xffffffffu, sv, off);
                float inv = 1.f / sv;
                M.wsm[lane]      = e0 * inv;
                M.wsm[lane + 32] = e1 * inv;
                M.wsm[lane + 64] = e2 * inv;
                M.wsm[lane + 96] = e3 * inv;
            }
            __syncthreads();
            if (tid < NND) {           // erase/add
                float wv = M.wsm[tid];
                float* mr = &M.mem[tid * 41];
                #pragma unroll
                for (int m = 0; m < MMD; m++)
                    mr[m] = mr[m] * (1.f - wv * M.ev[m]) + wv * M.av[m];
            }
            __syncthreads();
            if (tid < 320) {           // read r = w^T M, partials
                int m = tid >> 3, p = tid & 7;
                float sv = 0.f;
                #pragma unroll
                for (int n = p * 16; n < p * 16 + 16; n++)
                    sv += M.wsm[n] * M.mem[n * 41 + m];
                M.rred[tid] = sv;
            }
            __syncthreads();
            if (tid < MMD) {
                float sv = 0.f;
                #pragma unroll
                for (int p = 0; p < 8; p++) sv += M.rred[tid * 8 + p];
                g_r[hp][b][tid] = sv;
            }
            __syncthreads();
            if (tid == 0) {
                st_rel(&g_rflags[cta * 32], rb0 + (unsigned)(t + 1));
            }
        }
    } else {
        // =================== gemm CTA loop ===================
        GemmS& G = s.u.g;
        for (int t = 0; t < TT; t++) {
            const int hp = t & 1;
            // ---- part 1: finish gates with r(t-1) -> h(t) ----
            if (t > 0) {
                if (wrp == 0) {
                    unsigned tgt = rb0 + (unsigned)t;
                    for (;;) {
                        bool ok = true;
                        if (lane < NMEM)
                            ok = ((int)(ld_acq(&g_rflags[lane * 32]) - tgt) >= 0);
                        if (__all_sync(0xffffffffu, ok)) break;
                    }
                }
                __syncthreads();
                if (tid < 160) {       // stage r(t-1) into inp f4 slots 144..153
                    int b = tid / 10, q = tid - b * 10;
                    const float4* gr4 =
                        reinterpret_cast<const float4*>(&g_r[hp ^ 1][b][0]);
                    reinterpret_cast<float4*>(G.inp)[b * KP4 + 144 + q] =
                        __ldcg(gr4 + q);
                }
                __syncthreads();
            }
            if (tid < 64) {            // r-part (40 dims) folded into red
                const int kc = tid >> 4, tile = tid & 15;
                const int rg = tile & 3, bg = tile >> 2;
                const int roff = (kc < 2) ? 144 + kc * 3 : 150 + (kc - 2) * 2;
                const int rlen = (kc < 2) ? 3 : 2;
                const float4* W4 = reinterpret_cast<const float4*>(G.W);
                const float4* I4 = reinterpret_cast<const float4*>(G.inp);
                float a[20];
                float* rb = &G.red[(kc * 16 + tile) * RWS];
                #pragma unroll
                for (int q = 0; q < 20; q++) a[q] = rb[q];
                #pragma unroll 3
                for (int q = 0; q < rlen; q++) {
                    float4 wv[5], iv[4];
                    #pragma unroll
                    for (int i = 0; i < 5; i++)
                        wv[i] = W4[(rg + 4 * i) * KP4 + roff + q];
                    #pragma unroll
                    for (int j = 0; j < 4; j++)
                        iv[j] = I4[(bg + 4 * j) * KP4 + roff + q];
                    #pragma unroll
                    for (int i = 0; i < 5; i++) {
                        #pragma unroll
                        for (int j = 0; j < 4; j++) { DOT4(a[i * 4 + j], wv[i], iv[j]) }
                    }
                }
                #pragma unroll
                for (int q = 0; q < 20; q++) rb[q] = a[q];
            }
            __syncthreads();
            if (tid < RWS * BB) {      // reduce split-K
                int b = tid / RWS, lr = tid - b * RWS;
                int tile = (b & 3) * 4 + (lr & 3);
                int cell = (lr >> 2) * 4 + (b >> 2);
                float v = G.bias[lr];
                #pragma unroll
                for (int kc2 = 0; kc2 < 32; kc2++)
                    v += G.red[(kc2 * 16 + tile) * RWS + cell];
                G.gate[lr * BB + b] = v;
            }
            __syncthreads();
            if (tid < 5 * BB) {        // LSTM pointwise -> h(t)
                int b = tid / 5, hl = tid - b * 5;
                if (hl < cnt) {
                    float gv_i = G.gate[(0 + 4 * hl) * BB + b];
                    float gv_f = G.gate[(1 + 4 * hl) * BB + b];
                    float gv_g = G.gate[(2 + 4 * hl) * BB + b];
                    float gv_o = G.gate[(3 + 4 * hl) * BB + b];
                    float iv = 1.f / (1.f + expf(-gv_i));
                    float fv = 1.f / (1.f + expf(-gv_f));
                    float gv = tanhf(gv_g);
                    float ov = 1.f / (1.f + expf(-gv_o));
                    float cn = fv * G.cst[hl * BB + b] + iv * gv;
                    float hn = ov * tanhf(cn);
                    G.cst[hl * BB + b] = cn;
                    g_h[hp][b][hbase + hl] = hn;
                    if (t == TT - 1) {
                        out_h[b * HHD + hbase + hl] = hn;
                        out_c[b * HHD + hbase + hl] = cn;
                    }
                }
            }
            __syncthreads();
            if (tid == 0) {
                st_rel(&g_hflags[gi * 32], hb0 + (unsigned)(t + 1));
            }
            // ---- window B: prestage, fc(t), xh-gemm for t+1 ----
            wait_hflags(hb0 + (unsigned)(t + 1));
            for (int idx = tid; idx < BB * 144; idx += NTHR) {
                int b = idx / 144, q = idx - b * 144;
                float4 v;
                if (q < 16) {
                    v = (t + 1 < TT)
                        ? __ldg(reinterpret_cast<const float4*>(
                              &x[(b * TT + t + 1) * IND]) + q)
                        : make_float4(0.f, 0.f, 0.f, 0.f);
                } else {
                    v = __ldcg(reinterpret_cast<const float4*>(&g_h[hp][b][0])
                               + (q - 16));
                }
                reinterpret_cast<float4*>(G.inp)[b * KP4 + q] = v;
            }
            __syncthreads();
            {   // fc(t) from staged h
                int grp = tid >> 4, l16 = tid & 15;
                int d = gi + NGEMM * grp;
                bool valid = (d < 1024);
                int d2 = valid ? d : 0;
                int b = d2 >> 6, row = d2 & 63;
                const float4* w4 =
                    reinterpret_cast<const float4*>(W_fc + row * HHD);
                const float4* h4 =
                    reinterpret_cast<const float4*>(G.inp) + b * KP4 + 16;
                float acc = 0.f;
                #pragma unroll
                for (int q = 0; q < 8; q++) {
                    float4 wv = __ldg(w4 + l16 + 16 * q);
                    float4 hv = h4[l16 + 16 * q];
                    DOT4(acc, wv, hv)
                }
                #pragma unroll
                for (int off = 8; off; off >>= 1)
                    acc += __shfl_xor_sync(0xffffffffu, acc, off);
                if (valid && l16 == 0)
                    out_O[(b * TT + t) * OUTD + row] = tanhf(acc + b_fc[row]);
            }
            if (t + 1 < TT) gemm_xh(G, tid);
        }
        if (cta == NCTA - 1 && tid == 0) {
            st_rel(&g_gen, gen + 1);   // next launch's flag base
        }
    }
}

extern "C" void kernel_launch(void* const* d_in, const int* in_sizes, int n_in,
                              void* d_out, int out_size) {
    (void)in_sizes; (void)n_in; (void)out_size;
    cudaFuncSetAttribute(ntm_kernel,
                         cudaFuncAttributeMaxDynamicSharedMemorySize,
                         (int)sizeof(Smem));
    ntm_kernel<<<NCTA, NTHR, sizeof(Smem)>>>(
        (const float*)d_in[0],  (const float*)d_in[1],  (const float*)d_in[2],
        (const float*)d_in[3],  (const float*)d_in[4],  (const float*)d_in[5],
        (const float*)d_in[6],  (const float*)d_in[7],  (const float*)d_in[8],
        (const float*)d_in[9],  (const float*)d_in[10], (const float*)d_in[11],
        (const float*)d_in[12], (const float*)d_in[13], (const float*)d_in[14],
        (const float*)d_in[15], (const float*)d_in[16], (const float*)d_in[17],
        (const float*)d_in[18], (float*)d_out);
}

// round 17
// speedup vs baseline: 1.5735x; 1.0033x over previous
#include <cuda_runtime.h>
#include <math.h>

#define BB 16
#define TT 1024
#define IND 64
#define OUTD 64
#define HHD 512
#define NND 128
#define MMD 40
#define KTOT 616        // IND + HHD + MMD, order [x|h|r]
#define KP4  157        // padded row stride in float4
#define KPAD 628
#define NCTA 128
#define NMEM 16
#define NGEMM 112
#define NTHR 512
#define RWS 20          // gate rows per gemm CTA
#define EPSV 1e-8f
#define RCACHE 80       // projection rows cached in smem (of 121)

// ---------------- persistent global state ----------------
__device__ __align__(16) float g_h[2][BB][HHD];
__device__ __align__(16) float g_r[2][BB][MMD];
__device__ unsigned g_hflags[NGEMM * 32];  // h(t)-ready, one per gemm CTA
__device__ unsigned g_rflags[NMEM * 32];   // r(t)-ready, one per mem CTA
__device__ unsigned g_gen = 0;             // launch generation

static __device__ __forceinline__ unsigned ld_acq(const unsigned* p) {
    unsigned v;
    asm volatile("ld.acquire.gpu.global.u32 %0, [%1];" : "=r"(v) : "l"(p) : "memory");
    return v;
}
static __device__ __forceinline__ void st_rel(unsigned* p, unsigned v) {
    asm volatile("st.release.gpu.global.u32 [%0], %1;" :: "l"(p), "r"(v) : "memory");
}

// Wait until all NGEMM h-flags >= k. Warp 0 polls, then CTA-wide sync.
static __device__ __forceinline__ void wait_hflags(unsigned k) {
    if (threadIdx.x < 32) {
        for (;;) {
            bool ok = true;
            #pragma unroll
            for (int q = 0; q < 4; q++) {
                int f = threadIdx.x + 32 * q;
                if (f < NGEMM)
                    ok &= ((int)(ld_acq(&g_hflags[f * 32]) - k) >= 0);
            }
            if (__all_sync(0xffffffffu, ok)) break;
        }
    }
    __syncthreads();
}

struct __align__(16) GemmS {
    alignas(16) float W[RWS * KPAD];       // gate-weight slice [x|h|r]
    alignas(16) float inp[BB * KPAD];      // staged [x|h|r]
    alignas(16) float red[32 * 16 * RWS];  // split-K partials
    float gate[RWS * BB];
    float bias[RWS];
    float cst[5 * BB];
};
struct __align__(16) MemS {
    alignas(16) float pw[RCACHE * HHD];    // projection weight rows
    float mem[NND * 41];
    float rred[320];
    float proj[NND];
    float key[MMD];
    float ev[MMD];
    float av[MMD];
    float z[NND];
    float wsm[NND];
    float scal[4];                         // [0]=||key||+eps, [1]=beta
};
struct __align__(16) Smem {
    union { GemmS g; MemS m; } u;
    unsigned genv;
};

static __device__ __forceinline__ const float* prow(int r,
    const float* W_k, const float* W_b, const float* W_e, const float* W_a)
{
    if (r < 40)  return W_k + r * HHD;
    if (r == 40) return W_b;
    if (r <= 80) return W_e + (r - 41) * HHD;
    return W_a + (r - 81) * HHD;
}

#define DOT4(acc, wv, iv) \
    acc += wv.x*iv.x; acc += wv.y*iv.y; acc += wv.z*iv.z; acc += wv.w*iv.w;

// xh-part GEMM (576 dims = f4 0..143), conflict-free interleaved mapping.
static __device__ __forceinline__ void gemm_xh(GemmS& G, int tid) {
    const int kc = tid >> 4, tile = tid & 15;
    const int rg = tile & 3, bg = tile >> 2;
    const int koff = (kc < 16) ? kc * 5 : 80 + (kc - 16) * 4;
    const int klen = (kc < 16) ? 5 : 4;
    const float4* W4 = reinterpret_cast<const float4*>(G.W);
    const float4* I4 = reinterpret_cast<const float4*>(G.inp);
    float a[20];
    #pragma unroll
    for (int q = 0; q < 20; q++) a[q] = 0.f;
    #pragma unroll 5
    for (int q = 0; q < klen; q++) {
        float4 wv[5], iv[4];
        #pragma unroll
        for (int i = 0; i < 5; i++) wv[i] = W4[(rg + 4 * i) * KP4 + koff + q];
        #pragma unroll
        for (int j = 0; j < 4; j++) iv[j] = I4[(bg + 4 * j) * KP4 + koff + q];
        #pragma unroll
        for (int i = 0; i < 5; i++) {
            #pragma unroll
            for (int j = 0; j < 4; j++) { DOT4(a[i * 4 + j], wv[i], iv[j]) }
        }
    }
    float* rb = &G.red[(kc * 16 + tile) * RWS];
    #pragma unroll
    for (int q = 0; q < 20; q++) rb[q] = a[q];
}

__global__ void __launch_bounds__(NTHR, 1) ntm_kernel(
    const float* __restrict__ x,    const float* __restrict__ h0,
    const float* __restrict__ c0,   const float* __restrict__ mem0,
    const float* __restrict__ r0_,  const float* __restrict__ W_ih,
    const float* __restrict__ b_ih, const float* __restrict__ W_hh,
    const float* __restrict__ b_hh, const float* __restrict__ W_fc,
    const float* __restrict__ b_fc, const float* __restrict__ W_e,
    const float* __restrict__ b_e,  const float* __restrict__ W_a,
    const float* __restrict__ b_a,  const float* __restrict__ W_k,
    const float* __restrict__ b_k,  const float* __restrict__ W_b,
    const float* __restrict__ b_b,  float* __restrict__ out)
{
    extern __shared__ unsigned char smem_raw[];
    Smem& s = *reinterpret_cast<Smem*>(smem_raw);
    const int cta = blockIdx.x;
    const int tid = threadIdx.x;
    const int lane = tid & 31, wrp = tid >> 5;

    float* out_O = out;
    float* out_h = out + (size_t)BB * TT * OUTD;
    float* out_c = out_h + BB * HHD;

    if (tid == 0) s.genv = ld_acq(&g_gen);

    const bool is_mem = (cta < NMEM);
    const int gi = cta - NMEM;
    const int cnt   = (gi < 64) ? 5 : 4;
    const int hbase = (gi < 64) ? gi * 5 : 320 + (gi - 64) * 4;

    // ---------------- init ----------------
    if (!is_mem) {
        GemmS& G = s.u.g;
        for (int idx = tid; idx < RWS * KPAD; idx += NTHR) {
            int lr = idx / KPAD, k = idx - lr * KPAD;
            int g = lr & 3, hl = lr >> 2;
            float v = 0.f;
            if (hl < cnt) {
                int gr = g * HHD + hbase + hl;
                if (k < IND)             v = W_ih[gr * (IND + MMD) + k];
                else if (k < IND + HHD)  v = W_hh[gr * HHD + (k - IND)];
                else if (k < KTOT)       v = W_ih[gr * (IND + MMD) + IND + (k - IND - HHD)];
            }
            G.W[idx] = v;
        }
        if (tid < RWS) {
            int g = tid & 3, hl = tid >> 2;
            G.bias[tid] = (hl < cnt)
                ? (b_ih[g * HHD + hbase + hl] + b_hh[g * HHD + hbase + hl]) : 0.f;
        }
        if (tid < 5 * BB) {
            int b = tid / 5, hl = tid - b * 5;
            G.cst[hl * BB + b] = (hl < cnt) ? c0[b * HHD + hbase + hl] : 0.f;
        }
        for (int idx = tid; idx < BB * KPAD; idx += NTHR) {
            int b = idx / KPAD, k = idx - b * KPAD;
            float v = 0.f;
            if (k < IND)             v = x[(b * TT) * IND + k];
            else if (k < IND + HHD)  v = h0[b * HHD + (k - IND)];
            else if (k < KTOT)       v = r0_[b * MMD + (k - IND - HHD)];
            G.inp[idx] = v;
        }
        __syncthreads();
        gemm_xh(G, tid);               // xh partials for t = 0
    } else {
        MemS& M = s.u.m;
        for (int idx = tid; idx < RCACHE * HHD; idx += NTHR) {
            int r = idx >> 9, k = idx & (HHD - 1);
            M.pw[idx] = prow(r, W_k, W_b, W_e, W_a)[k];
        }
        for (int idx = tid; idx < NND * MMD; idx += NTHR) {
            int n = idx / MMD, m = idx - n * MMD;
            M.mem[n * 41 + m] = mem0[cta * NND * MMD + idx];
        }
    }
    __syncthreads();
    const unsigned gen = s.genv;
    const unsigned hb0 = gen * (unsigned)TT;        // h-flag base this launch
    const unsigned rb0 = gen * (unsigned)(TT - 1);  // r-flag base this launch

    if (is_mem) {
        // =================== memory CTA loop ===================
        MemS& M = s.u.m;
        const int b = cta;
        for (int t = 0; t < TT - 1; t++) {
            const int hp = t & 1;
            wait_hflags(hb0 + (unsigned)(t + 1));
            {   // 121-row projection GEMV over h(t)
                const float4* h4 = reinterpret_cast<const float4*>(&g_h[hp][b][0]);
                float4 hv0 = __ldcg(h4 + lane);
                float4 hv1 = __ldcg(h4 + lane + 32);
                float4 hv2 = __ldcg(h4 + lane + 64);
                float4 hv3 = __ldcg(h4 + lane + 96);
                #pragma unroll
                for (int jr = 0; jr < 8; jr++) {
                    int r = wrp + 16 * jr;
                    if (r <= 120) {                       // warp-uniform
                        float4 a0, a1, a2, a3;
                        if (r < RCACHE) {
                            const float4* w4 = reinterpret_cast<const float4*>(&M.pw[r * HHD]);
                            a0 = w4[lane]; a1 = w4[lane + 32];
                            a2 = w4[lane + 64]; a3 = w4[lane + 96];
                        } else {
                            const float4* w4 = reinterpret_cast<const float4*>(
                                prow(r, W_k, W_b, W_e, W_a));
                            a0 = __ldg(w4 + lane); a1 = __ldg(w4 + lane + 32);
                            a2 = __ldg(w4 + lane + 64); a3 = __ldg(w4 + lane + 96);
                        }
                        float acc = 0.f;
                        DOT4(acc, a0, hv0) DOT4(acc, a1, hv1)
                        DOT4(acc, a2, hv2) DOT4(acc, a3, hv3)
                        #pragma unroll
                        for (int off = 16; off; off >>= 1)
                            acc += __shfl_xor_sync(0xffffffffu, acc, off);
                        if (lane == 0) M.proj[r] = acc;
                    }
                }
            }
            __syncthreads();
            if (tid < 121) {
                float v = M.proj[tid];
                if (tid < 40) {
                    M.key[tid] = tanhf(v + b_k[tid]);
                } else if (tid == 40) {
                    float zz = v + b_b[0];
                    M.scal[1] = fmaxf(zz, 0.f) + log1pf(expf(-fabsf(zz))) + EPSV;
                } else if (tid <= 80) {
                    int m = tid - 41;
                    M.ev[m] = 1.f / (1.f + expf(-(v + b_e[m])));
                } else {
                    int m = tid - 81;
                    M.av[m] = tanhf(v + b_a[m]);
                }
            }
            __syncthreads();
            if (tid < NND) {
                const float* mr = &M.mem[tid * 41];
                float dot = 0.f, nrm = 0.f;
                #pragma unroll
                for (int m = 0; m < MMD; m++) {
                    float mv = mr[m];
                    dot += mv * M.key[m];
                    nrm += mv * mv;
                }
                M.z[tid] = dot / (sqrtf(nrm) + EPSV);
            } else if (wrp == 8) {
                float v = 0.f;
                if (lane < MMD)      { float kv = M.key[lane];      v  = kv * kv; }
                if (lane + 32 < MMD) { float kv = M.key[lane + 32]; v += kv * kv; }
                #pragma unroll
                for (int off = 16; off; off >>= 1)
                    v += __shfl_xor_sync(0xffffffffu, v, off);
                if (lane == 0) M.scal[0] = sqrtf(v) + EPSV;
            }
            __syncthreads();
            if (wrp == 0) {            // softmax, one warp
                float bscale = M.scal[1] / M.scal[0];
                float z0 = M.z[lane]      * bscale;
                float z1 = M.z[lane + 32] * bscale;
                float z2 = M.z[lane + 64] * bscale;
                float z3 = M.z[lane + 96] * bscale;
                float mx = fmaxf(fmaxf(z0, z1), fmaxf(z2, z3));
                #pragma unroll
                for (int off = 16; off; off >>= 1)
                    mx = fmaxf(mx, __shfl_xor_sync(0xffffffffu, mx, off));
                float e0 = expf(z0 - mx), e1 = expf(z1 - mx);
                float e2 = expf(z2 - mx), e3 = expf(z3 - mx);
                float sv = e0 + e1 + e2 + e3;
                #pragma unroll
                for (int off = 16; off; off >>= 1)
                    sv += __shfl_xor_sync(0xffffffffu, sv, off);
                float inv = 1.f / sv;
                M.wsm[lane]      = e0 * inv;
                M.wsm[lane + 32] = e1 * inv;
                M.wsm[lane + 64] = e2 * inv;
                M.wsm[lane + 96] = e3 * inv;
            }
            __syncthreads();
            // ---- fused erase/add + read partials: each (n,m) visited once ----
            if (tid < 320) {
                int m = tid >> 3, p = tid & 7;
                float em = M.ev[m], am = M.av[m];
                float sv = 0.f;
                #pragma unroll
                for (int n = p * 16; n < p * 16 + 16; n++) {
                    float w = M.wsm[n];
                    float mv = M.mem[n * 41 + m];
                    float upd = mv * (1.f - w * em) + w * am;
                    M.mem[n * 41 + m] = upd;
                    sv += w * upd;
                }
                M.rred[tid] = sv;
            }
            __syncthreads();
            if (tid < MMD) {
                float sv = 0.f;
                #pragma unroll
                for (int p = 0; p < 8; p++) sv += M.rred[tid * 8 + p];
                g_r[hp][b][tid] = sv;
            }
            __syncthreads();
            if (tid == 0) {
                st_rel(&g_rflags[cta * 32], rb0 + (unsigned)(t + 1));
            }
        }
    } else {
        // =================== gemm CTA loop ===================
        GemmS& G = s.u.g;
        for (int t = 0; t < TT; t++) {
            const int hp = t & 1;
            // ---- part 1: finish gates with r(t-1) -> h(t) ----
            if (t > 0) {
                if (wrp == 0) {
                    unsigned tgt = rb0 + (unsigned)t;
                    for (;;) {
                        bool ok = true;
                        if (lane < NMEM)
                            ok = ((int)(ld_acq(&g_rflags[lane * 32]) - tgt) >= 0);
                        if (__all_sync(0xffffffffu, ok)) break;
                    }
                }
                __syncthreads();
                if (tid < 160) {       // stage r(t-1) into inp f4 slots 144..153
                    int b = tid / 10, q = tid - b * 10;
                    const float4* gr4 =
                        reinterpret_cast<const float4*>(&g_r[hp ^ 1][b][0]);
                    reinterpret_cast<float4*>(G.inp)[b * KP4 + 144 + q] =
                        __ldcg(gr4 + q);
                }
                __syncthreads();
            }
            if (tid < 64) {            // r-part (40 dims) folded into red
                const int kc = tid >> 4, tile = tid & 15;
                const int rg = tile & 3, bg = tile >> 2;
                const int roff = (kc < 2) ? 144 + kc * 3 : 150 + (kc - 2) * 2;
                const int rlen = (kc < 2) ? 3 : 2;
                const float4* W4 = reinterpret_cast<const float4*>(G.W);
                const float4* I4 = reinterpret_cast<const float4*>(G.inp);
                float a[20];
                float* rb = &G.red[(kc * 16 + tile) * RWS];
                #pragma unroll
                for (int q = 0; q < 20; q++) a[q] = rb[q];
                #pragma unroll 3
                for (int q = 0; q < rlen; q++) {
                    float4 wv[5], iv[4];
                    #pragma unroll
                    for (int i = 0; i < 5; i++)
                        wv[i] = W4[(rg + 4 * i) * KP4 + roff + q];
                    #pragma unroll
                    for (int j = 0; j < 4; j++)
                        iv[j] = I4[(bg + 4 * j) * KP4 + roff + q];
                    #pragma unroll
                    for (int i = 0; i < 5; i++) {
                        #pragma unroll
                        for (int j = 0; j < 4; j++) { DOT4(a[i * 4 + j], wv[i], iv[j]) }
                    }
                }
                #pragma unroll
                for (int q = 0; q < 20; q++) rb[q] = a[q];
            }
            __syncthreads();
            if (tid < RWS * BB) {      // reduce split-K
                int b = tid / RWS, lr = tid - b * RWS;
                int tile = (b & 3) * 4 + (lr & 3);
                int cell = (lr >> 2) * 4 + (b >> 2);
                float v = G.bias[lr];
                #pragma unroll
                for (int kc2 = 0; kc2 < 32; kc2++)
                    v += G.red[(kc2 * 16 + tile) * RWS + cell];
                G.gate[lr * BB + b] = v;
            }
            __syncthreads();
            if (tid < 5 * BB) {        // LSTM pointwise -> h(t)
                int b = tid / 5, hl = tid - b * 5;
                if (hl < cnt) {
                    float gv_i = G.gate[(0 + 4 * hl) * BB + b];
                    float gv_f = G.gate[(1 + 4 * hl) * BB + b];
                    float gv_g = G.gate[(2 + 4 * hl) * BB + b];
                    float gv_o = G.gate[(3 + 4 * hl) * BB + b];
                    float iv = 1.f / (1.f + expf(-gv_i));
                    float fv = 1.f / (1.f + expf(-gv_f));
                    float gv = tanhf(gv_g);
                    float ov = 1.f / (1.f + expf(-gv_o));
                    float cn = fv * G.cst[hl * BB + b] + iv * gv;
                    float hn = ov * tanhf(cn);
                    G.cst[hl * BB + b] = cn;
                    g_h[hp][b][hbase + hl] = hn;
                    if (t == TT - 1) {
                        out_h[b * HHD + hbase + hl] = hn;
                        out_c[b * HHD + hbase + hl] = cn;
                    }
                }
            }
            __syncthreads();
            if (tid == 0) {
                st_rel(&g_hflags[gi * 32], hb0 + (unsigned)(t + 1));
            }
            // ---- window B: prestage, fc(t), xh-gemm for t+1 ----
            wait_hflags(hb0 + (unsigned)(t + 1));
            for (int idx = tid; idx < BB * 144; idx += NTHR) {
                int b = idx / 144, q = idx - b * 144;
                float4 v;
                if (q < 16) {
                    v = (t + 1 < TT)
                        ? __ldg(reinterpret_cast<const float4*>(
                              &x[(b * TT + t + 1) * IND]) + q)
                        : make_float4(0.f, 0.f, 0.f, 0.f);
                } else {
                    v = __ldcg(reinterpret_cast<const float4*>(&g_h[hp][b][0])
                               + (q - 16));
                }
                reinterpret_cast<float4*>(G.inp)[b * KP4 + q] = v;
            }
            __syncthreads();
            {   // fc(t) from staged h
                int grp = tid >> 4, l16 = tid & 15;
                int d = gi + NGEMM * grp;
                bool valid = (d < 1024);
                int d2 = valid ? d : 0;
                int b = d2 >> 6, row = d2 & 63;
                const float4* w4 =
                    reinterpret_cast<const float4*>(W_fc + row * HHD);
                const float4* h4 =
                    reinterpret_cast<const float4*>(G.inp) + b * KP4 + 16;
                float acc = 0.f;
                #pragma unroll
                for (int q = 0; q < 8; q++) {
                    float4 wv = __ldg(w4 + l16 + 16 * q);
                    float4 hv = h4[l16 + 16 * q];
                    DOT4(acc, wv, hv)
                }
                #pragma unroll
                for (int off = 8; off; off >>= 1)
                    acc += __shfl_xor_sync(0xffffffffu, acc, off);
                if (valid && l16 == 0)
                    out_O[(b * TT + t) * OUTD + row] = tanhf(acc + b_fc[row]);
            }
            if (t + 1 < TT) gemm_xh(G, tid);
        }
        if (cta == NCTA - 1 && tid == 0) {
            st_rel(&g_gen, gen + 1);   // next launch's flag base
        }
    }
}

extern "C" void kernel_launch(void* const* d_in, const int* in_sizes, int n_in,
                              void* d_out, int out_size) {
    (void)in_sizes; (void)n_in; (void)out_size;
    cudaFuncSetAttribute(ntm_kernel,
                         cudaFuncAttributeMaxDynamicSharedMemorySize,
                         (int)sizeof(Smem));
    ntm_kernel<<<NCTA, NTHR, sizeof(Smem)>>>(
        (const float*)d_in[0],  (const float*)d_in[1],  (const float*)d_in[2],
        (const float*)d_in[3],  (const float*)d_in[4],  (const float*)d_in[5],
        (const float*)d_in[6],  (const float*)d_in[7],  (const float*)d_in[8],
        (const float*)d_in[9],  (const float*)d_in[10], (const float*)d_in[11],
        (const float*)d_in[12], (const float*)d_in[13], (const float*)d_in[14],
        (const float*)d_in[15], (const float*)d_in[16], (const float*)d_in[17],
        (const float*)d_in[18], (float*)d_out);
}